// round 7
// baseline (speedup 1.0000x reference)
#include <cuda_runtime.h>
#include <cuda_bf16.h>
#include <math.h>

#define BB   64
#define TT   512
#define DD   1024
#define HH   1024
#define N3H  3072
#define MM   (BB * TT)     // 32768
#define KP   512           // K/2 packed u32 pairs
#define ZROW MM            // zero-row index in hbuf
#define NBLK 148

// ---------------------------------------------------------------------------
// Scratch (device globals)
// ---------------------------------------------------------------------------
__device__ float    g_gi[(size_t)MM * N3H];
__device__ unsigned g_xhi[(size_t)MM * KP];
__device__ unsigned g_xlo[(size_t)MM * KP];
__device__ unsigned g_wihhi[(size_t)N3H * KP];
__device__ unsigned g_wihlo[(size_t)N3H * KP];
__device__ unsigned g_whhhi[(size_t)N3H * KP];
__device__ unsigned g_whhlo[(size_t)N3H * KP];
__device__ unsigned g_hbhi[(size_t)(MM + 1) * KP];   // packed masked h per row; row MM = zeros
__device__ unsigned g_hblo[(size_t)(MM + 1) * KP];
__device__ unsigned g_rows[MM];
__device__ unsigned g_asrc[MM];
__device__ int      g_off[516];
__device__ int      g_ndepth;
__device__ unsigned g_bar;

// ---------------------------------------------------------------------------
// helpers
// ---------------------------------------------------------------------------
__device__ __forceinline__ void pack2(float v0, float v1, unsigned& hi, unsigned& lo)
{
    __nv_bfloat16 h0 = __float2bfloat16(v0);
    __nv_bfloat16 h1 = __float2bfloat16(v1);
    float r0 = v0 - __bfloat162float(h0);
    float r1 = v1 - __bfloat162float(h1);
    __nv_bfloat16 l0 = __float2bfloat16(r0);
    __nv_bfloat16 l1 = __float2bfloat16(r1);
    hi = (unsigned)__bfloat16_as_ushort(h0) | ((unsigned)__bfloat16_as_ushort(h1) << 16);
    lo = (unsigned)__bfloat16_as_ushort(l0) | ((unsigned)__bfloat16_as_ushort(l1) << 16);
}

__device__ __forceinline__ void mma_bf16(float* d,
    unsigned a0, unsigned a1, unsigned a2, unsigned a3,
    unsigned b0, unsigned b1)
{
    asm volatile(
        "mma.sync.aligned.m16n8k16.row.col.f32.bf16.bf16.f32 "
        "{%0,%1,%2,%3},{%4,%5,%6,%7},{%8,%9},{%0,%1,%2,%3};\n"
        : "+f"(d[0]), "+f"(d[1]), "+f"(d[2]), "+f"(d[3])
        : "r"(a0), "r"(a1), "r"(a2), "r"(a3), "r"(b0), "r"(b1));
}

__device__ __forceinline__ void cp_async16(unsigned saddr, const void* gptr)
{
    asm volatile("cp.async.cg.shared.global [%0], [%1], 16;\n" :: "r"(saddr), "l"(gptr));
}
#define CP_COMMIT()  asm volatile("cp.async.commit_group;\n" ::: "memory")
#define CP_WAIT(N)   asm volatile("cp.async.wait_group %0;\n" :: "n"(N) : "memory")

__device__ __forceinline__ float sigf(float x) { return 1.0f / (1.0f + expf(-x)); }

__device__ __forceinline__ unsigned ld_acquire_u32(unsigned* p)
{
    unsigned v;
    asm volatile("ld.acquire.gpu.u32 %0, [%1];" : "=r"(v) : "l"(p) : "memory");
    return v;
}

// ---------------------------------------------------------------------------
// Fused prep: packs x/Wih/Whh, packs h0 into hbuf, zeroes zero-row,
// resets barrier, and bucket-sorts rows by segment depth.
// ---------------------------------------------------------------------------
#define NB_X     65536                    // MM*KP/256
#define NB_W     6144                     // N3H*KP/256
#define NB_H0    128                      // BB*KP/256
#define B_WIH    (NB_X)
#define B_WHH    (NB_X + NB_W)
#define B_H0     (NB_X + 2 * NB_W)
#define B_ZERO   (B_H0 + NB_H0)
#define B_PRE    (B_ZERO + 1)
#define NB_PREP  (B_PRE + 1)

__global__ __launch_bounds__(256) void prep_kernel(
    const float* __restrict__ x,
    const float* __restrict__ h0,
    const int*   __restrict__ dones,
    const float* __restrict__ Wih,
    const float* __restrict__ Whh)
{
    const int blk = blockIdx.x;
    const int tid = threadIdx.x;

    if (blk < B_WIH) {                               // pack x
        size_t i = (size_t)blk * 256 + tid;
        float2 v = ((const float2*)x)[i];
        unsigned h, l; pack2(v.x, v.y, h, l);
        g_xhi[i] = h; g_xlo[i] = l;
    } else if (blk < B_WHH) {                        // pack W_ih
        size_t i = (size_t)(blk - B_WIH) * 256 + tid;
        float2 v = ((const float2*)Wih)[i];
        unsigned h, l; pack2(v.x, v.y, h, l);
        g_wihhi[i] = h; g_wihlo[i] = l;
    } else if (blk < B_H0) {                         // pack W_hh
        size_t i = (size_t)(blk - B_WHH) * 256 + tid;
        float2 v = ((const float2*)Whh)[i];
        unsigned h, l; pack2(v.x, v.y, h, l);
        g_whhhi[i] = h; g_whhlo[i] = l;
    } else if (blk < B_ZERO) {                       // pack h0 -> hbuf row b*TT
        int i = (blk - B_H0) * 256 + tid;            // 0..BB*KP-1
        int b = i >> 9, p = i & 511;
        float v0 = h0[b * HH + 2 * p];
        float v1 = h0[b * HH + 2 * p + 1];
        float m = 1.0f - (float)dones[b * TT];
        unsigned h, l; pack2(v0 * m, v1 * m, h, l);
        g_hbhi[(size_t)(b * TT) * KP + p] = h;
        g_hblo[(size_t)(b * TT) * KP + p] = l;
    } else if (blk == B_ZERO) {                      // zero-row + barrier reset
        g_hbhi[(size_t)ZROW * KP + tid]       = 0u;
        g_hbhi[(size_t)ZROW * KP + 256 + tid] = 0u;
        g_hblo[(size_t)ZROW * KP + tid]       = 0u;
        g_hblo[(size_t)ZROW * KP + 256 + tid] = 0u;
        if (tid == 0) g_bar = 0u;
    } else {                                         // depth bucketing
        __shared__ int cnt[513];
        __shared__ int maxd;
        for (int i = tid; i < 513; i += 256) cnt[i] = 0;
        if (tid == 0) maxd = 0;
        __syncthreads();
        if (tid < 64) {
            int b = tid, dep = 0, lmax = 0;
            for (int t = 0; t < TT; ++t) {
                int dn = dones[b * TT + t];
                dep = (t == 0) ? 0 : (dn ? 0 : dep + 1);
                atomicAdd(&cnt[dep], 1);
                if (dep > lmax) lmax = dep;
            }
            atomicMax(&maxd, lmax);
        }
        __syncthreads();
        if (tid == 0) {
            int nd = maxd + 1;
            g_ndepth = nd;
            int acc = 0;
            for (int d = 0; d <= nd; ++d) {
                g_off[d] = acc;
                int c = (d < nd) ? cnt[d] : 0;
                cnt[d] = acc;                 // becomes fill counter
                acc += c;
            }
        }
        __syncthreads();
        if (tid < 64) {
            int b = tid, dep = 0;
            for (int t = 0; t < TT; ++t) {
                int r = b * TT + t;
                int dn = dones[r];
                dep = (t == 0) ? 0 : (dn ? 0 : dep + 1);
                int pos = atomicAdd(&cnt[dep], 1);
                g_rows[pos] = (unsigned)r;
                g_asrc[pos] = (t > 0 && dn) ? (unsigned)ZROW : (unsigned)r;
            }
        }
    }
}

__global__ void dummy_kernel() {}

// ---------------------------------------------------------------------------
// gi GEMM (unchanged, proven): g_gi = x @ W_ih^T + b_ih, bf16 hi/lo 3 passes
// ---------------------------------------------------------------------------
__global__ __launch_bounds__(512) void gi_gemm_kernel(const float* __restrict__ bias)
{
    __shared__ unsigned sAh[128][20], sAl[128][20], sBh[128][20], sBl[128][20];

    const int tid  = threadIdx.x;
    const int lane = tid & 31;
    const int wid  = tid >> 5;
    const int n0   = blockIdx.x * 128;
    const int m0   = blockIdx.y * 128;
    const int mw   = (wid & 3) * 32;
    const int nw   = (wid >> 2) * 32;
    const int g    = lane >> 2;
    const int t4   = lane & 3;

    float Da[8][4], Db[8][4];
#pragma unroll
    for (int i = 0; i < 8; ++i)
#pragma unroll
        for (int j = 0; j < 4; ++j) { Da[i][j] = 0.f; Db[i][j] = 0.f; }

    const int lrow = tid >> 2;
    const int lq   = (tid & 3) * 4;

    for (int c = 0; c < 32; ++c) {
        size_t abase = (size_t)(m0 + lrow) * KP + c * 16 + lq;
        size_t bbase = (size_t)(n0 + lrow) * KP + c * 16 + lq;
        *(uint4*)&sAh[lrow][lq] = *(const uint4*)&g_xhi[abase];
        *(uint4*)&sAl[lrow][lq] = *(const uint4*)&g_xlo[abase];
        *(uint4*)&sBh[lrow][lq] = *(const uint4*)&g_wihhi[bbase];
        *(uint4*)&sBl[lrow][lq] = *(const uint4*)&g_wihlo[bbase];
        __syncthreads();

#pragma unroll
        for (int kt = 0; kt < 2; ++kt) {
            const int o = kt * 8;
            unsigned ahi[2][4], alo[2][4], bhi[4][2];
#pragma unroll
            for (int mt = 0; mt < 2; ++mt) {
                int r = mw + mt * 16 + g;
                ahi[mt][0] = sAh[r][o + t4];     ahi[mt][1] = sAh[r + 8][o + t4];
                ahi[mt][2] = sAh[r][o + 4 + t4]; ahi[mt][3] = sAh[r + 8][o + 4 + t4];
                alo[mt][0] = sAl[r][o + t4];     alo[mt][1] = sAl[r + 8][o + t4];
                alo[mt][2] = sAl[r][o + 4 + t4]; alo[mt][3] = sAl[r + 8][o + 4 + t4];
            }
#pragma unroll
            for (int nt = 0; nt < 4; ++nt) {
                int rn = nw + nt * 8 + g;
                bhi[nt][0] = sBh[rn][o + t4];
                bhi[nt][1] = sBh[rn][o + 4 + t4];
            }
#pragma unroll
            for (int nt = 0; nt < 4; ++nt)
#pragma unroll
                for (int mt = 0; mt < 2; ++mt)
                    mma_bf16(Da[nt * 2 + mt], ahi[mt][0], ahi[mt][1], ahi[mt][2], ahi[mt][3],
                             bhi[nt][0], bhi[nt][1]);
#pragma unroll
            for (int nt = 0; nt < 4; ++nt)
#pragma unroll
                for (int mt = 0; mt < 2; ++mt)
                    mma_bf16(Db[nt * 2 + mt], alo[mt][0], alo[mt][1], alo[mt][2], alo[mt][3],
                             bhi[nt][0], bhi[nt][1]);
#pragma unroll
            for (int nt = 0; nt < 4; ++nt) {
                int rn = nw + nt * 8 + g;
                unsigned bl0 = sBl[rn][o + t4];
                unsigned bl1 = sBl[rn][o + 4 + t4];
#pragma unroll
                for (int mt = 0; mt < 2; ++mt)
                    mma_bf16(Db[nt * 2 + mt], ahi[mt][0], ahi[mt][1], ahi[mt][2], ahi[mt][3],
                             bl0, bl1);
            }
        }
        __syncthreads();
    }

#pragma unroll
    for (int nt = 0; nt < 4; ++nt) {
        int col = n0 + nw + nt * 8 + 2 * t4;
        float bs0 = bias[col], bs1 = bias[col + 1];
#pragma unroll
        for (int mt = 0; mt < 2; ++mt) {
            int idx = nt * 2 + mt;
            int row = m0 + mw + mt * 16 + g;
            g_gi[(size_t)row * N3H + col]           = Da[idx][0] + Db[idx][0] + bs0;
            g_gi[(size_t)row * N3H + col + 1]       = Da[idx][1] + Db[idx][1] + bs1;
            g_gi[(size_t)(row + 8) * N3H + col]     = Da[idx][2] + Db[idx][2] + bs0;
            g_gi[(size_t)(row + 8) * N3H + col + 1] = Da[idx][3] + Db[idx][3] + bs1;
        }
    }
}

// ---------------------------------------------------------------------------
// Segment-parallel GRU: persistent 148 blocks x 512 threads, loops over
// depths; per depth processes tiles [128 gathered rows x 64 j x 3 gates].
// SMEM u32 layout: [0..127] sRows, [128..255] sAsrc,
//   SAOFF: A staging [2buf][2arr][128][20], SWOFF: W staging [2][2][192][20].
//   gh output (float [128][196]) aliases staging at SAOFF.
// ---------------------------------------------------------------------------
#define HDR   256
#define SAOFF HDR
#define SWOFF (HDR + 2 * 2 * 128 * 20)          // 10496
#define SMEM_U32 (SWOFF + 2 * 2 * 192 * 20)     // 25856

__device__ __forceinline__ void issue_chunk(
    unsigned* smem, unsigned smem_sa, int wid, int lane, int ch, int buf, int j0)
{
#pragma unroll
    for (int r0 = 0; r0 < 2; ++r0) {             // A: 8 rows x 2 arr x 4 q
        int idx  = r0 * 32 + lane;
        int rowl = wid * 8 + (idx >> 3);
        int arr  = (idx >> 2) & 1;
        int q    = idx & 3;
        unsigned asrc = smem[128 + rowl];
        const unsigned* src = (arr ? g_hblo : g_hbhi) + (size_t)asrc * KP + ch * 16 + q * 4;
        unsigned dst = smem_sa + (SAOFF + ((buf * 2 + arr) * 128 + rowl) * 20 + q * 4) * 4;
        cp_async16(dst, src);
    }
#pragma unroll
    for (int r0 = 0; r0 < 3; ++r0) {             // W: 12 n-rows x 2 arr x 4 q
        int idx = r0 * 32 + lane;
        int n   = wid * 12 + (idx >> 3);
        int arr = (idx >> 2) & 1;
        int q   = idx & 3;
        int jj  = n / 3;
        int gate = n - jj * 3;
        const unsigned* src = (arr ? g_whhlo : g_whhhi)
            + (size_t)(gate * HH + j0 + jj) * KP + ch * 16 + q * 4;
        unsigned dst = smem_sa + (SWOFF + ((buf * 2 + arr) * 192 + n) * 20 + q * 4) * 4;
        cp_async16(dst, src);
    }
    CP_COMMIT();
}

__global__ __launch_bounds__(512, 1) void gru_seg_kernel(
    const float* __restrict__ h0in,
    const int*   __restrict__ dones,
    const float* __restrict__ bhh,
    float*       __restrict__ out)
{
    extern __shared__ unsigned smem[];
    float* sGh = (float*)(smem + SAOFF);
    const unsigned smem_sa = (unsigned)__cvta_generic_to_shared(smem);

    float* hlast = out + (size_t)MM * HH;

    const int tid  = threadIdx.x;
    const int lane = tid & 31;
    const int wid  = tid >> 5;
    const int g    = lane >> 2;
    const int t4   = lane & 3;
    const int mw   = wid & 3;       // 4 m-warps of 32 rows
    const int nw   = wid >> 2;      // 4 n-warps of 48 cols
    const int bid  = blockIdx.x;

    const int nd = g_ndepth;

    for (int d = 0; d < nd; ++d) {
        const int off = g_off[d];
        const int Md  = g_off[d + 1] - off;
        const int tiles = ((Md + 127) >> 7) << 4;

        for (int tile = bid; tile < tiles; tile += NBLK) {
            const int mt = tile >> 4;
            const int nt = tile & 15;
            const int j0 = nt * 64;

            if (tid < 128) {
                int ri = off + mt * 128 + tid;
                unsigned r = 0xFFFFFFFFu, a = (unsigned)ZROW;
                if (ri < off + Md) { r = g_rows[ri]; a = g_asrc[ri]; }
                smem[tid] = r; smem[128 + tid] = a;
            }
            __syncthreads();

            float D[2][6][4];
#pragma unroll
            for (int mf = 0; mf < 2; ++mf)
#pragma unroll
                for (int nf = 0; nf < 6; ++nf)
#pragma unroll
                    for (int c = 0; c < 4; ++c) D[mf][nf][c] = 0.f;

            issue_chunk(smem, smem_sa, wid, lane, 0, 0, j0);
            issue_chunk(smem, smem_sa, wid, lane, 1, 1, j0);

            for (int ch = 0; ch < 32; ++ch) {
                if (ch < 31) { CP_WAIT(1); } else { CP_WAIT(0); }
                __syncthreads();
                const int buf = ch & 1;
                const int abase = SAOFF + (buf * 2) * 128 * 20;
                const int wbase = SWOFF + (buf * 2) * 192 * 20;

#pragma unroll
                for (int kf = 0; kf < 2; ++kf) {
                    const int o = kf * 8;
                    unsigned AH[2][4], AL[2][4];
#pragma unroll
                    for (int mf = 0; mf < 2; ++mf) {
                        int row = mw * 32 + mf * 16 + g;
                        AH[mf][0] = smem[abase + row * 20 + o + t4];
                        AH[mf][1] = smem[abase + (row + 8) * 20 + o + t4];
                        AH[mf][2] = smem[abase + row * 20 + o + 4 + t4];
                        AH[mf][3] = smem[abase + (row + 8) * 20 + o + 4 + t4];
                        AL[mf][0] = smem[abase + (128 + row) * 20 + o + t4];
                        AL[mf][1] = smem[abase + (128 + row + 8) * 20 + o + t4];
                        AL[mf][2] = smem[abase + (128 + row) * 20 + o + 4 + t4];
                        AL[mf][3] = smem[abase + (128 + row + 8) * 20 + o + 4 + t4];
                    }
                    unsigned BH[6][2], BL[6][2];
#pragma unroll
                    for (int nf = 0; nf < 6; ++nf) {
                        int n = nw * 48 + nf * 8 + g;
                        BH[nf][0] = smem[wbase + n * 20 + o + t4];
                        BH[nf][1] = smem[wbase + n * 20 + o + 4 + t4];
                        BL[nf][0] = smem[wbase + (192 + n) * 20 + o + t4];
                        BL[nf][1] = smem[wbase + (192 + n) * 20 + o + 4 + t4];
                    }
#pragma unroll
                    for (int nf = 0; nf < 6; ++nf)
#pragma unroll
                        for (int mf = 0; mf < 2; ++mf)
                            mma_bf16(D[mf][nf], AH[mf][0], AH[mf][1], AH[mf][2], AH[mf][3],
                                     BH[nf][0], BH[nf][1]);
#pragma unroll
                    for (int nf = 0; nf < 6; ++nf)
#pragma unroll
                        for (int mf = 0; mf < 2; ++mf)
                            mma_bf16(D[mf][nf], AH[mf][0], AH[mf][1], AH[mf][2], AH[mf][3],
                                     BL[nf][0], BL[nf][1]);
#pragma unroll
                    for (int nf = 0; nf < 6; ++nf)
#pragma unroll
                        for (int mf = 0; mf < 2; ++mf)
                            mma_bf16(D[mf][nf], AL[mf][0], AL[mf][1], AL[mf][2], AL[mf][3],
                                     BH[nf][0], BH[nf][1]);
                }
                __syncthreads();
                if (ch + 2 < 32)
                    issue_chunk(smem, smem_sa, wid, lane, ch + 2, ch & 1, j0);
            }

            // ---- write gh to SMEM ----
            __syncthreads();
#pragma unroll
            for (int mf = 0; mf < 2; ++mf)
#pragma unroll
                for (int nf = 0; nf < 6; ++nf) {
                    int rr = mw * 32 + mf * 16 + g;
                    int cc = nw * 48 + nf * 8 + 2 * t4;
                    sGh[rr * 196 + cc]           = D[mf][nf][0];
                    sGh[rr * 196 + cc + 1]       = D[mf][nf][1];
                    sGh[(rr + 8) * 196 + cc]     = D[mf][nf][2];
                    sGh[(rr + 8) * 196 + cc + 1] = D[mf][nf][3];
                }
            __syncthreads();

            // ---- fused GRU epilogue: thread = (row, 16-jj group) ----
            {
                const int rowl = tid >> 2;
                const int q    = tid & 3;
                unsigned r = smem[rowl];
                if (r != 0xFFFFFFFFu) {
                    const int t = (int)(r & 511);
                    const int b = (int)(r >> 9);
                    const int dn = dones[r];
                    const float m = 1.0f - (float)dn;
                    const float* hp = (t == 0) ? (h0in + (size_t)b * HH)
                                               : (out + (size_t)(r - 1) * HH);
                    const bool hread = (t == 0) || (dn == 0);
                    const float nm = (t < 511) ? (1.0f - (float)dones[r + 1]) : 1.0f;
                    const int jbase = j0 + q * 16;
                    unsigned phi[8], plo[8];

#pragma unroll
                    for (int grp = 0; grp < 4; ++grp) {
                        const int j = jbase + grp * 4;
                        float4 gr4 = *(const float4*)&g_gi[(size_t)r * N3H + j];
                        float4 gz4 = *(const float4*)&g_gi[(size_t)r * N3H + HH + j];
                        float4 gn4 = *(const float4*)&g_gi[(size_t)r * N3H + 2 * HH + j];
                        float4 brv = *(const float4*)&bhh[j];
                        float4 bzv = *(const float4*)&bhh[HH + j];
                        float4 bnv = *(const float4*)&bhh[2 * HH + j];
                        float4 hp4 = make_float4(0.f, 0.f, 0.f, 0.f);
                        if (hread) hp4 = *(const float4*)&hp[j];

                        float hn[4];
                        const float* gr = &gr4.x; const float* gz = &gz4.x;
                        const float* gn = &gn4.x; const float* br = &brv.x;
                        const float* bz = &bzv.x; const float* bn = &bnv.x;
                        const float* hpv = &hp4.x;
#pragma unroll
                        for (int e = 0; e < 4; ++e) {
                            const int jj = q * 16 + grp * 4 + e;
                            float ghr = sGh[rowl * 196 + jj * 3 + 0];
                            float ghz = sGh[rowl * 196 + jj * 3 + 1];
                            float ghn = sGh[rowl * 196 + jj * 3 + 2];
                            float rv = sigf(gr[e] + ghr + br[e]);
                            float zv = sigf(gz[e] + ghz + bz[e]);
                            float nv = tanhf(gn[e] + rv * (ghn + bn[e]));
                            hn[e] = (1.f - zv) * nv + zv * (hpv[e] * m);
                        }
                        float4 o4 = make_float4(hn[0], hn[1], hn[2], hn[3]);
                        *(float4*)&out[(size_t)r * HH + j] = o4;
                        if (t == 511)
                            *(float4*)&hlast[(size_t)b * HH + j] = o4;
                        pack2(hn[0] * nm, hn[1] * nm, phi[grp * 2],     plo[grp * 2]);
                        pack2(hn[2] * nm, hn[3] * nm, phi[grp * 2 + 1], plo[grp * 2 + 1]);
                    }
                    if (t < 511) {
                        size_t hb = (size_t)(r + 1) * KP + (jbase >> 1);
                        *(uint4*)&g_hbhi[hb]     = make_uint4(phi[0], phi[1], phi[2], phi[3]);
                        *(uint4*)&g_hbhi[hb + 4] = make_uint4(phi[4], phi[5], phi[6], phi[7]);
                        *(uint4*)&g_hblo[hb]     = make_uint4(plo[0], plo[1], plo[2], plo[3]);
                        *(uint4*)&g_hblo[hb + 4] = make_uint4(plo[4], plo[5], plo[6], plo[7]);
                    }
                }
            }
            __syncthreads();
        }

        // ---- grid barrier between depths ----
        if (d + 1 < nd) {
            if (tid == 0) {
                asm volatile("red.release.gpu.add.u32 [%0], %1;"
                             :: "l"(&g_bar), "r"(1u) : "memory");
                const unsigned target = (unsigned)NBLK * (unsigned)(d + 1);
                while (ld_acquire_u32(&g_bar) < target) { }
            }
            __syncthreads();
        }
    }
}

// ---------------------------------------------------------------------------
// launch
// ---------------------------------------------------------------------------
extern "C" void kernel_launch(void* const* d_in, const int* in_sizes, int n_in,
                              void* d_out, int out_size)
{
    const float* x     = (const float*)d_in[0];
    const float* h0    = (const float*)d_in[1];
    const int*   dones = (const int*)  d_in[2];
    const float* Wih   = (const float*)d_in[3];
    const float* Whh   = (const float*)d_in[4];
    const float* bih   = (const float*)d_in[5];
    const float* bhh   = (const float*)d_in[6];

    float* out = (float*)d_out;

    const int SEG_SMEM = SMEM_U32 * 4;   // 103,424 B
    cudaFuncSetAttribute(gru_seg_kernel, cudaFuncAttributeMaxDynamicSharedMemorySize, SEG_SMEM);

    prep_kernel<<<NB_PREP, 256>>>(x, h0, dones, Wih, Whh);

    {
        dim3 grid(N3H / 128, MM / 128);
        gi_gemm_kernel<<<grid, 512>>>(bih);
    }

    dummy_kernel<<<1, 32>>>();

    gru_seg_kernel<<<NBLK, 512, SEG_SMEM>>>(h0, dones, bhh, out);
}